// round 10
// baseline (speedup 1.0000x reference)
#include <cuda_runtime.h>
#include <cuda_bf16.h>
#include <cstdint>

// Problem constants
#define B_    64
#define TK_   2048
#define KD_   512
#define U_    1024
#define H_    8
#define D_    128
#define TT_   128          // t rows per block tile
#define KPAD_ 520          // key smem row pitch (bf16): 1040B, 260 words %32 = 4
#define WKPAD_ 72          // wk  smem row pitch (bf16): 144B, 36 words %32 = 4
#define WKSTG_ 18432       // one wk stage: 128 rows * 144B
#define NT_MAIN 512

// Scratch (static __device__ arrays; no allocation)
__device__ float          g_qb[B_ * U_];        // q proj + bq + bk
__device__ __nv_bfloat16  g_wkb[U_ * KD_];      // Wk in bf16

// Shared memory layout (bytes)
#define SM_KEYS   0                              // 128*520*2      = 133120
#define SM_WK     133120                         // 4*18432        = 73728
#define SM_QB     206848                         // 1024 f32
#define SM_NV     210944                         // 128 f32
#define SM_ADD    211456                         // 8*128 f32
#define SM_TMP    215552                         // 16 B
#define SM_TOTAL  215568

// ---------------------------------------------------------------------------
__device__ __forceinline__ uint32_t smem_u32(const void* p) {
    uint32_t a;
    asm("{ .reg .u64 t; cvta.to.shared.u64 t, %1; cvt.u32.u64 %0, t; }" : "=r"(a) : "l"(p));
    return a;
}
__device__ __forceinline__ float tanh_fast(float x) {
    float y;
    asm("tanh.approx.f32 %0, %1;" : "=f"(y) : "f"(x));
    return y;
}
#define LDSM4(r0, r1, r2, r3, addr) \
    asm volatile("ldmatrix.sync.aligned.m8n8.x4.shared.b16 {%0,%1,%2,%3}, [%4];" \
                 : "=r"(r0), "=r"(r1), "=r"(r2), "=r"(r3) : "r"(addr))

// ---------------------------------------------------------------------------
// Fused prep: blocks [0,512) qproj, [512,1024) wkconv, [1024,1280) zero out
// zero: 64*8*512 = 262144 floats = 65536 float4 = 256 blocks x 256 threads
__global__ void prep_kernel(const float* __restrict__ query,
                            const float* __restrict__ Wq,
                            const float* __restrict__ bq,
                            const float* __restrict__ bk,
                            const float* __restrict__ Wk,
                            float* __restrict__ out) {
    int bid = blockIdx.x;
    int tid = threadIdx.x;
    if (bid < 512) {
        // q[b,u] = query[b,:].Wq[u,:] + bq[u] + bk[u]
        int b = bid >> 3, oct = bid & 7;
        int lane = tid & 31, w = tid >> 5;
        __shared__ float qs[KD_];
        for (int i = tid; i < KD_; i += 256) qs[i] = query[b * KD_ + i];
        __syncthreads();
        for (int it = 0; it < 16; ++it) {
            int u = oct * 128 + it * 8 + w;
            const float* wr = Wq + (size_t)u * KD_;
            float p = 0.f;
            #pragma unroll 4
            for (int k = lane; k < KD_; k += 32) p += qs[k] * wr[k];
            p += __shfl_xor_sync(~0u, p, 16);
            p += __shfl_xor_sync(~0u, p, 8);
            p += __shfl_xor_sync(~0u, p, 4);
            p += __shfl_xor_sync(~0u, p, 2);
            p += __shfl_xor_sync(~0u, p, 1);
            if (lane == 0) g_qb[b * U_ + u] = p + bq[u] + bk[u];
        }
    } else if (bid < 1024) {
        int i4 = (bid - 512) * 256 + tid;       // 131072 float4 groups
        float4 f = ((const float4*)Wk)[i4];
        __nv_bfloat162 p0 = __floats2bfloat162_rn(f.x, f.y);
        __nv_bfloat162 p1 = __floats2bfloat162_rn(f.z, f.w);
        uint2 val = make_uint2(*(uint32_t*)&p0, *(uint32_t*)&p1);
        *(uint2*)(g_wkb + (size_t)i4 * 4) = val;
    } else {
        int i4 = (bid - 1024) * 256 + tid;      // 65536 float4 groups = 262144 floats
        ((float4*)out)[i4] = make_float4(0.f, 0.f, 0.f, 0.f);
    }
}

// ---------------------------------------------------------------------------
__global__ void __launch_bounds__(NT_MAIN, 1)
main_kernel(const float* __restrict__ key,
            const float* __restrict__ v,
            float* __restrict__ out) {
    extern __shared__ char smem[];
    const uint32_t smb = smem_u32(smem);
    __nv_bfloat16* keys = (__nv_bfloat16*)(smem + SM_KEYS);
    float* qb_s  = (float*)(smem + SM_QB);
    float* nv_s  = (float*)(smem + SM_NV);
    float* add_s = (float*)(smem + SM_ADD);
    float* tmp_s = (float*)(smem + SM_TMP);

    int bid = blockIdx.x;
    int b = bid >> 4, tt = bid & 15;
    int tid = threadIdx.x, lane = tid & 31, w = tid >> 5;   // 16 warps
    int wm = w & 3, wn = w >> 2;   // 4 warps on M (32 rows), 4 on N (32 cols)

    const float* keyg = key + ((size_t)(b * TK_ + tt * TT_)) * KD_;

    // ---- init phase ----
    {   // key tile fp32 -> bf16 smem (pitch KPAD_)
        const float4* kg4 = (const float4*)keyg;
        for (int i = tid; i < TT_ * KD_ / 4; i += NT_MAIN) {
            int row = i >> 7, c4 = i & 127;
            float4 f = kg4[row * 128 + c4];
            __nv_bfloat162* dst = (__nv_bfloat162*)(keys + row * KPAD_ + c4 * 4);
            dst[0] = __floats2bfloat162_rn(f.x, f.y);
            dst[1] = __floats2bfloat162_rn(f.z, f.w);
        }
    }
    for (int i = tid; i < U_; i += NT_MAIN) qb_s[i] = g_qb[b * U_ + i];
    for (int i = tid; i < H_ * TT_; i += NT_MAIN) add_s[i] = 0.f;
    if (w == 0) {
        float p = 0.f;
        #pragma unroll
        for (int j = 0; j < 4; ++j) { float x = v[lane + 32 * j]; p += x * x; }
        p += __shfl_xor_sync(~0u, p, 16);
        p += __shfl_xor_sync(~0u, p, 8);
        p += __shfl_xor_sync(~0u, p, 4);
        p += __shfl_xor_sync(~0u, p, 2);
        p += __shfl_xor_sync(~0u, p, 1);
        if (lane == 0) tmp_s[0] = rsqrtf(p) * 0.08838834764831845f;  // 1/sqrt(128)
    }
    __syncthreads();
    if (tid < D_) nv_s[tid] = v[tid] * tmp_s[0];

    // ---- wk chunk prefetch: chunk c -> head c>>3, k-range (c&7)*64; stage c&3
    auto prefetch = [&](int c) {
        if (c < 64) {
            int h = c >> 3, kc = c & 7;
            const __nv_bfloat16* src = g_wkb + (size_t)h * D_ * KD_ + kc * 64;
            uint32_t dst0 = smb + SM_WK + (c & 3) * WKSTG_;
            #pragma unroll
            for (int j = 0; j < 2; ++j) {
                int i = tid + j * NT_MAIN;
                int r = i >> 3, g = i & 7;
                const void* gp = src + (size_t)r * KD_ + g * 8;
                asm volatile("cp.async.cg.shared.global [%0], [%1], 16;"
                             :: "r"(dst0 + r * (WKPAD_ * 2) + g * 16), "l"(gp));
            }
        }
        asm volatile("cp.async.commit_group;");
    };

    // ldmatrix base addresses
    // A (keys): lane l -> row wm*32 + mt*16 + (l&15), col k + (l>>4)*8
    uint32_t a_base = smb + SM_KEYS
                    + (uint32_t)(wm * 32 + (lane & 15)) * (KPAD_ * 2)
                    + (uint32_t)(lane >> 4) * 16;
    // B (wk): lane l -> row wn*32 + p*16 + (l&7) + ((l>>4)&1)*8, col k + ((l>>3)&1)*8
    uint32_t b_base = smb + SM_WK
                    + (uint32_t)(wn * 32 + (lane & 7) + ((lane >> 4) & 1) * 8) * (WKPAD_ * 2)
                    + (uint32_t)((lane >> 3) & 1) * 16;

    float c_[2][4][4];
    #pragma unroll
    for (int mt = 0; mt < 2; ++mt)
        #pragma unroll
        for (int nt = 0; nt < 4; ++nt)
            #pragma unroll
            for (int e = 0; e < 4; ++e) c_[mt][nt][e] = 0.f;

    prefetch(0); prefetch(1); prefetch(2);

    for (int c = 0; c < 64; ++c) {
        asm volatile("cp.async.wait_group 2;");
        __syncthreads();
        prefetch(c + 3);

        uint32_t bst = b_base + (c & 3) * WKSTG_;
        int kbase = (c & 7) * 64;

        #pragma unroll
        for (int ks = 0; ks < 4; ++ks) {
            uint32_t a[2][4], bb[2][4];
            uint32_t ao = a_base + (uint32_t)(kbase + ks * 16) * 2;
            LDSM4(a[0][0], a[0][1], a[0][2], a[0][3], ao);
            LDSM4(a[1][0], a[1][1], a[1][2], a[1][3], ao + 16 * (KPAD_ * 2));
            uint32_t bo = bst + (uint32_t)(ks * 16) * 2;
            #pragma unroll
            for (int p = 0; p < 2; ++p)
                LDSM4(bb[p][0], bb[p][1], bb[p][2], bb[p][3],
                      bo + (uint32_t)(p * 16) * (WKPAD_ * 2));
            #pragma unroll
            for (int mt = 0; mt < 2; ++mt)
                #pragma unroll
                for (int nt = 0; nt < 4; ++nt) {
                    uint32_t b0 = (nt & 1) ? bb[nt >> 1][2] : bb[nt >> 1][0];
                    uint32_t b1 = (nt & 1) ? bb[nt >> 1][3] : bb[nt >> 1][1];
                    asm volatile(
                        "mma.sync.aligned.m16n8k16.row.col.f32.bf16.bf16.f32 "
                        "{%0,%1,%2,%3}, {%4,%5,%6,%7}, {%8,%9}, {%0,%1,%2,%3};\n"
                        : "+f"(c_[mt][nt][0]), "+f"(c_[mt][nt][1]),
                          "+f"(c_[mt][nt][2]), "+f"(c_[mt][nt][3])
                        : "r"(a[mt][0]), "r"(a[mt][1]), "r"(a[mt][2]), "r"(a[mt][3]),
                          "r"(b0), "r"(b1));
                }
        }

        if ((c & 7) == 7) {
            // epilogue: add_s[h][t] += sum_u nv[u] * tanh(kp + q)
            int h = c >> 3;
            const float* qh = qb_s + h * D_;
            #pragma unroll
            for (int mt = 0; mt < 2; ++mt) {
                float slo = 0.f, shi = 0.f;
                #pragma unroll
                for (int nt = 0; nt < 4; ++nt) {
                    int u0 = wn * 32 + nt * 8 + (lane & 3) * 2;
                    float q0 = qh[u0], q1 = qh[u0 + 1];
                    float n0 = nv_s[u0], n1 = nv_s[u0 + 1];
                    slo += n0 * tanh_fast(c_[mt][nt][0] + q0)
                         + n1 * tanh_fast(c_[mt][nt][1] + q1);
                    shi += n0 * tanh_fast(c_[mt][nt][2] + q0)
                         + n1 * tanh_fast(c_[mt][nt][3] + q1);
                    c_[mt][nt][0] = 0.f; c_[mt][nt][1] = 0.f;
                    c_[mt][nt][2] = 0.f; c_[mt][nt][3] = 0.f;
                }
                slo += __shfl_xor_sync(~0u, slo, 1);
                slo += __shfl_xor_sync(~0u, slo, 2);
                shi += __shfl_xor_sync(~0u, shi, 1);
                shi += __shfl_xor_sync(~0u, shi, 2);
                if ((lane & 3) == 0) {
                    int r = wm * 32 + mt * 16 + (lane >> 2);
                    atomicAdd(&add_s[h * TT_ + r], slo);
                    atomicAdd(&add_s[h * TT_ + r + 8], shi);
                }
            }
        }
    }
    __syncthreads();

    // ---- softmax over heads (legacy dim=1) ----
    if (tid < TT_) {
        float av[H_];
        float m = -1e30f;
        #pragma unroll
        for (int h = 0; h < H_; ++h) { av[h] = add_s[h * TT_ + tid]; m = fmaxf(m, av[h]); }
        float s = 0.f;
        #pragma unroll
        for (int h = 0; h < H_; ++h) { av[h] = __expf(av[h] - m); s += av[h]; }
        float inv = __fdividef(1.0f, s);
        #pragma unroll
        for (int h = 0; h < H_; ++h) add_s[h * TT_ + tid] = av[h] * inv;
    }
    __syncthreads();

    // ---- context: out[b,h,d] += sum_t w[h,t] * key[t,d] (fp32 key from L2) ----
    {
        float acc[H_];
        #pragma unroll
        for (int h = 0; h < H_; ++h) acc[h] = 0.f;
        for (int t = 0; t < TT_; ++t) {
            float kv = keyg[(size_t)t * KD_ + tid];
            #pragma unroll
            for (int h = 0; h < H_; ++h) acc[h] += add_s[h * TT_ + t] * kv;
        }
        float* ob = out + (size_t)b * (H_ * KD_) + tid;
        #pragma unroll
        for (int h = 0; h < H_; ++h) atomicAdd(&ob[h * KD_], acc[h]);
    }
}

// ---------------------------------------------------------------------------
extern "C" void kernel_launch(void* const* d_in, const int* in_sizes, int n_in,
                              void* d_out, int out_size) {
    const float* query = (const float*)d_in[0];
    const float* key   = (const float*)d_in[1];
    const float* Wq    = (const float*)d_in[2];
    const float* bq    = (const float*)d_in[3];
    const float* Wk    = (const float*)d_in[4];
    const float* bk    = (const float*)d_in[5];
    const float* v     = (const float*)d_in[6];
    float* out = (float*)d_out;

    prep_kernel<<<1280, 256>>>(query, Wq, bq, bk, Wk, out);

    cudaFuncSetAttribute(main_kernel,
                         cudaFuncAttributeMaxDynamicSharedMemorySize, SM_TOTAL);
    main_kernel<<<B_ * (TK_ / TT_), NT_MAIN, SM_TOTAL>>>(key, v, out);
}

// round 12
// speedup vs baseline: 1.0031x; 1.0031x over previous
#include <cuda_runtime.h>
#include <cuda_bf16.h>
#include <cstdint>

// Problem constants
#define B_    64
#define TK_   2048
#define KD_   512
#define U_    1024
#define H_    8
#define D_    128
#define TT_   128          // t rows per block tile
#define KPAD_ 520          // key smem row pitch (bf16): 1040B, 260 words %32 = 4
#define WKPAD_ 72          // wk  smem row pitch (bf16): 144B, 36 words %32 = 4
#define WKSTG_ 18432       // one wk stage: 128 rows * 144B
#define NT_MAIN 256

// Scratch (static __device__ arrays; no allocation)
__device__ float          g_qb[B_ * U_];        // q proj + bq + bk
__device__ __nv_bfloat16  g_wkb[U_ * KD_];      // Wk in bf16

// Shared memory layout (bytes)
#define SM_KEYS   0                              // 128*520*2      = 133120
#define SM_WK     133120                         // 4*18432        = 73728
#define SM_QB     206848                         // 1024 f32
#define SM_NV     210944                         // 128 f32
#define SM_ADD    211456                         // 8*128 f32
#define SM_TMP    215552                         // 16 B
#define SM_TOTAL  215568

// ---------------------------------------------------------------------------
__device__ __forceinline__ uint32_t smem_u32(const void* p) {
    uint32_t a;
    asm("{ .reg .u64 t; cvta.to.shared.u64 t, %1; cvt.u32.u64 %0, t; }" : "=r"(a) : "l"(p));
    return a;
}
__device__ __forceinline__ float tanh_fast(float x) {
    float y;
    asm("tanh.approx.f32 %0, %1;" : "=f"(y) : "f"(x));
    return y;
}
#define LDSM4(r0, r1, r2, r3, addr) \
    asm volatile("ldmatrix.sync.aligned.m8n8.x4.shared.b16 {%0,%1,%2,%3}, [%4];" \
                 : "=r"(r0), "=r"(r1), "=r"(r2), "=r"(r3) : "r"(addr))
#define MMA16816(c0, c1, c2, c3, a0, a1, a2, a3, b0, b1) \
    asm volatile("mma.sync.aligned.m16n8k16.row.col.f32.bf16.bf16.f32 " \
                 "{%0,%1,%2,%3}, {%4,%5,%6,%7}, {%8,%9}, {%0,%1,%2,%3};" \
                 : "+f"(c0), "+f"(c1), "+f"(c2), "+f"(c3) \
                 : "r"(a0), "r"(a1), "r"(a2), "r"(a3), "r"(b0), "r"(b1))

// ---------------------------------------------------------------------------
// Fused prep: blocks [0,512) qproj, [512,1024) wkconv, [1024,1280) zero out
__global__ void prep_kernel(const float* __restrict__ query,
                            const float* __restrict__ Wq,
                            const float* __restrict__ bq,
                            const float* __restrict__ bk,
                            const float* __restrict__ Wk,
                            float* __restrict__ out) {
    int bid = blockIdx.x;
    int tid = threadIdx.x;
    if (bid < 512) {
        int b = bid >> 3, oct = bid & 7;
        int lane = tid & 31, w = tid >> 5;
        __shared__ float qs[KD_];
        for (int i = tid; i < KD_; i += 256) qs[i] = query[b * KD_ + i];
        __syncthreads();
        for (int it = 0; it < 16; ++it) {
            int u = oct * 128 + it * 8 + w;
            const float* wr = Wq + (size_t)u * KD_;
            float p = 0.f;
            #pragma unroll 4
            for (int k = lane; k < KD_; k += 32) p += qs[k] * wr[k];
            p += __shfl_xor_sync(~0u, p, 16);
            p += __shfl_xor_sync(~0u, p, 8);
            p += __shfl_xor_sync(~0u, p, 4);
            p += __shfl_xor_sync(~0u, p, 2);
            p += __shfl_xor_sync(~0u, p, 1);
            if (lane == 0) g_qb[b * U_ + u] = p + bq[u] + bk[u];
        }
    } else if (bid < 1024) {
        int i4 = (bid - 512) * 256 + tid;       // 131072 float4 groups
        float4 f = ((const float4*)Wk)[i4];
        __nv_bfloat162 p0 = __floats2bfloat162_rn(f.x, f.y);
        __nv_bfloat162 p1 = __floats2bfloat162_rn(f.z, f.w);
        uint2 val = make_uint2(*(uint32_t*)&p0, *(uint32_t*)&p1);
        *(uint2*)(g_wkb + (size_t)i4 * 4) = val;
    } else {
        int i4 = (bid - 1024) * 256 + tid;      // 65536 float4 = 262144 floats
        ((float4*)out)[i4] = make_float4(0.f, 0.f, 0.f, 0.f);
    }
}

// ---------------------------------------------------------------------------
__global__ void __launch_bounds__(NT_MAIN, 1)
main_kernel(const float* __restrict__ key,
            const float* __restrict__ v,
            float* __restrict__ out) {
    extern __shared__ char smem[];
    const uint32_t smb = smem_u32(smem);
    __nv_bfloat16* keys = (__nv_bfloat16*)(smem + SM_KEYS);
    float* qb_s  = (float*)(smem + SM_QB);
    float* nv_s  = (float*)(smem + SM_NV);
    float* add_s = (float*)(smem + SM_ADD);
    float* tmp_s = (float*)(smem + SM_TMP);

    int bid = blockIdx.x;
    int b = bid >> 4, tt = bid & 15;
    int tid = threadIdx.x, lane = tid & 31, w = tid >> 5;   // 8 warps
    int wm = w & 1, wn = w >> 1;   // 2 warps on M (64 rows), 4 on N (32 cols)

    const float* keyg = key + ((size_t)(b * TK_ + tt * TT_)) * KD_;

    // ---- init phase ----
    {   // key tile fp32 -> bf16 smem (pitch KPAD_)
        const float4* kg4 = (const float4*)keyg;
        for (int i = tid; i < TT_ * KD_ / 4; i += NT_MAIN) {
            int row = i >> 7, c4 = i & 127;
            float4 f = kg4[row * 128 + c4];
            __nv_bfloat162* dst = (__nv_bfloat162*)(keys + row * KPAD_ + c4 * 4);
            dst[0] = __floats2bfloat162_rn(f.x, f.y);
            dst[1] = __floats2bfloat162_rn(f.z, f.w);
        }
    }
    for (int i = tid; i < U_; i += NT_MAIN) qb_s[i] = g_qb[b * U_ + i];
    for (int i = tid; i < H_ * TT_; i += NT_MAIN) add_s[i] = 0.f;
    if (w == 0) {
        float p = 0.f;
        #pragma unroll
        for (int j = 0; j < 4; ++j) { float x = v[lane + 32 * j]; p += x * x; }
        p += __shfl_xor_sync(~0u, p, 16);
        p += __shfl_xor_sync(~0u, p, 8);
        p += __shfl_xor_sync(~0u, p, 4);
        p += __shfl_xor_sync(~0u, p, 2);
        p += __shfl_xor_sync(~0u, p, 1);
        if (lane == 0) tmp_s[0] = rsqrtf(p) * 0.08838834764831845f;  // 1/sqrt(128)
    }
    __syncthreads();
    if (tid < D_) nv_s[tid] = v[tid] * tmp_s[0];

    // ---- wk chunk prefetch: chunk c -> head c>>3, k-range (c&7)*64; stage c&3
    auto prefetch = [&](int c) {
        if (c < 64) {
            int h = c >> 3, kc = c & 7;
            const __nv_bfloat16* src = g_wkb + (size_t)h * D_ * KD_ + kc * 64;
            uint32_t dst0 = smb + SM_WK + (c & 3) * WKSTG_;
            #pragma unroll
            for (int j = 0; j < 4; ++j) {
                int i = tid + j * NT_MAIN;
                int r = i >> 3, g = i & 7;
                const void* gp = src + (size_t)r * KD_ + g * 8;
                asm volatile("cp.async.cg.shared.global [%0], [%1], 16;"
                             :: "r"(dst0 + r * (WKPAD_ * 2) + g * 16), "l"(gp));
            }
        }
        asm volatile("cp.async.commit_group;");
    };

    // ldmatrix base addresses
    // A (keys): lane l -> row wm*64 + mt*16 + (l&15), col k + (l>>4)*8
    uint32_t a_base = smb + SM_KEYS
                    + (uint32_t)(wm * 64 + (lane & 15)) * (KPAD_ * 2)
                    + (uint32_t)(lane >> 4) * 16;
    // B (wk): lane l -> row wn*32 + p*16 + (l&7) + ((l>>4)&1)*8, col k + ((l>>3)&1)*8
    uint32_t b_base = smb + SM_WK
                    + (uint32_t)(wn * 32 + (lane & 7) + ((lane >> 4) & 1) * 8) * (WKPAD_ * 2)
                    + (uint32_t)((lane >> 3) & 1) * 16;

    float c_[4][4][4];      // [mt][nt][e]
    #pragma unroll
    for (int mt = 0; mt < 4; ++mt)
        #pragma unroll
        for (int nt = 0; nt < 4; ++nt)
            #pragma unroll
            for (int e = 0; e < 4; ++e) c_[mt][nt][e] = 0.f;

    uint32_t af[2][4][4];   // [buf][mt][frag]
    uint32_t bf[2][2][4];   // [buf][p][frag]

    prefetch(0); prefetch(1); prefetch(2);

    for (int c = 0; c < 64; ++c) {
        asm volatile("cp.async.wait_group 2;");
        __syncthreads();
        prefetch(c + 3);

        uint32_t bst = b_base + (c & 3) * WKSTG_;
        uint32_t ast = a_base + (uint32_t)((c & 7) * 64) * 2;

        // load k-step 0 fragments into buf 0
        #pragma unroll
        for (int mt = 0; mt < 4; ++mt)
            LDSM4(af[0][mt][0], af[0][mt][1], af[0][mt][2], af[0][mt][3],
                  ast + (uint32_t)(mt * 16) * (KPAD_ * 2));
        #pragma unroll
        for (int p = 0; p < 2; ++p)
            LDSM4(bf[0][p][0], bf[0][p][1], bf[0][p][2], bf[0][p][3],
                  bst + (uint32_t)(p * 16) * (WKPAD_ * 2));

        #pragma unroll
        for (int ks = 0; ks < 4; ++ks) {
            int cur = ks & 1, nxt = cur ^ 1;
            if (ks < 3) {   // prefetch next k-step fragments
                uint32_t ao = ast + (uint32_t)((ks + 1) * 16) * 2;
                #pragma unroll
                for (int mt = 0; mt < 4; ++mt)
                    LDSM4(af[nxt][mt][0], af[nxt][mt][1], af[nxt][mt][2], af[nxt][mt][3],
                          ao + (uint32_t)(mt * 16) * (KPAD_ * 2));
                uint32_t bo = bst + (uint32_t)((ks + 1) * 16) * 2;
                #pragma unroll
                for (int p = 0; p < 2; ++p)
                    LDSM4(bf[nxt][p][0], bf[nxt][p][1], bf[nxt][p][2], bf[nxt][p][3],
                          bo + (uint32_t)(p * 16) * (WKPAD_ * 2));
            }
            #pragma unroll
            for (int mt = 0; mt < 4; ++mt)
                #pragma unroll
                for (int nt = 0; nt < 4; ++nt) {
                    uint32_t b0 = (nt & 1) ? bf[cur][nt >> 1][2] : bf[cur][nt >> 1][0];
                    uint32_t b1 = (nt & 1) ? bf[cur][nt >> 1][3] : bf[cur][nt >> 1][1];
                    MMA16816(c_[mt][nt][0], c_[mt][nt][1], c_[mt][nt][2], c_[mt][nt][3],
                             af[cur][mt][0], af[cur][mt][1], af[cur][mt][2], af[cur][mt][3],
                             b0, b1);
                }
        }

        if ((c & 7) == 7) {
            // epilogue: add_s[h][t] += sum_u nv[u] * tanh(kp + q)
            int h = c >> 3;
            const float* qh = qb_s + h * D_;
            #pragma unroll
            for (int mt = 0; mt < 4; ++mt) {
                float slo = 0.f, shi = 0.f;
                #pragma unroll
                for (int nt = 0; nt < 4; ++nt) {
                    int u0 = wn * 32 + nt * 8 + (lane & 3) * 2;
                    float q0 = qh[u0], q1 = qh[u0 + 1];
                    float n0 = nv_s[u0], n1 = nv_s[u0 + 1];
                    slo += n0 * tanh_fast(c_[mt][nt][0] + q0)
                         + n1 * tanh_fast(c_[mt][nt][1] + q1);
                    shi += n0 * tanh_fast(c_[mt][nt][2] + q0)
                         + n1 * tanh_fast(c_[mt][nt][3] + q1);
                    c_[mt][nt][0] = 0.f; c_[mt][nt][1] = 0.f;
                    c_[mt][nt][2] = 0.f; c_[mt][nt][3] = 0.f;
                }
                slo += __shfl_xor_sync(~0u, slo, 1);
                slo += __shfl_xor_sync(~0u, slo, 2);
                shi += __shfl_xor_sync(~0u, shi, 1);
                shi += __shfl_xor_sync(~0u, shi, 2);
                if ((lane & 3) == 0) {
                    int r = wm * 64 + mt * 16 + (lane >> 2);
                    atomicAdd(&add_s[h * TT_ + r], slo);
                    atomicAdd(&add_s[h * TT_ + r + 8], shi);
                }
            }
        }
    }
    __syncthreads();

    // ---- softmax over heads (legacy dim=1) ----
    if (tid < TT_) {
        float av[H_];
        float m = -1e30f;
        #pragma unroll
        for (int h = 0; h < H_; ++h) { av[h] = add_s[h * TT_ + tid]; m = fmaxf(m, av[h]); }
        float s = 0.f;
        #pragma unroll
        for (int h = 0; h < H_; ++h) { av[h] = __expf(av[h] - m); s += av[h]; }
        float inv = __fdividef(1.0f, s);
        #pragma unroll
        for (int h = 0; h < H_; ++h) add_s[h * TT_ + tid] = av[h] * inv;
    }
    __syncthreads();

    // ---- context: out[b,h,d] += sum_t w[h,t] * key[t,d] (fp32 key from L2) ----
    {
        float acc[H_][2];
        #pragma unroll
        for (int h = 0; h < H_; ++h) { acc[h][0] = 0.f; acc[h][1] = 0.f; }
        const float2* kg2 = (const float2*)keyg;
        for (int t = 0; t < TT_; ++t) {
            float2 kv = kg2[t * (KD_ / 2) + tid];
            #pragma unroll
            for (int h = 0; h < H_; ++h) {
                float wv = add_s[h * TT_ + t];
                acc[h][0] += wv * kv.x;
                acc[h][1] += wv * kv.y;
            }
        }
        float* ob = out + (size_t)b * (H_ * KD_) + tid * 2;
        #pragma unroll
        for (int h = 0; h < H_; ++h) {
            atomicAdd(&ob[h * KD_], acc[h][0]);
            atomicAdd(&ob[h * KD_ + 1], acc[h][1]);
        }
    }
}

// ---------------------------------------------------------------------------
extern "C" void kernel_launch(void* const* d_in, const int* in_sizes, int n_in,
                              void* d_out, int out_size) {
    const float* query = (const float*)d_in[0];
    const float* key   = (const float*)d_in[1];
    const float* Wq    = (const float*)d_in[2];
    const float* bq    = (const float*)d_in[3];
    const float* Wk    = (const float*)d_in[4];
    const float* bk    = (const float*)d_in[5];
    const float* v     = (const float*)d_in[6];
    float* out = (float*)d_out;

    prep_kernel<<<1280, 256>>>(query, Wq, bq, bk, Wk, out);

    cudaFuncSetAttribute(main_kernel,
                         cudaFuncAttributeMaxDynamicSharedMemorySize, SM_TOTAL);
    main_kernel<<<B_ * (TK_ / TT_), NT_MAIN, SM_TOTAL>>>(key, v, out);
}

// round 15
// speedup vs baseline: 1.2257x; 1.2219x over previous
#include <cuda_runtime.h>
#include <cuda_bf16.h>
#include <cstdint>

// Problem constants
#define B_    64
#define TK_   2048
#define KD_   512
#define U_    1024
#define H_    8
#define D_    128
#define TT_   128          // t rows per block tile
#define KPAD_ 520          // key smem row pitch (bf16): 1040B, 260 words %32 = 4
#define WKPAD_ 72          // wk  smem row pitch (bf16): 144B, 36 words %32 = 4
#define WKSTG_ 18432       // one wk stage: 128 rows * 144B
#define NT_MAIN 320        // 8 consumer warps + 2 producer warps

// Scratch (static __device__ arrays; no allocation)
__device__ float          g_qb[B_ * U_];        // q proj + bq + bk
__device__ __nv_bfloat16  g_wkb[U_ * KD_];      // Wk in bf16

// Shared memory layout (bytes)
#define SM_KEYS   0                              // 128*520*2      = 133120
#define SM_WK     133120                         // 4*18432        = 73728
#define SM_QB     206848                         // 1024 f32
#define SM_NV     210944                         // 128 f32
#define SM_ADD    211456                         // 8*128 f32
#define SM_TMP    215552                         // 16 B
#define SM_MBAR   215568                         // 8 mbarriers x 8B
#define SM_TOTAL  215632

#define MB_FULL(s)   (SM_MBAR + (s) * 8)         // producer cp.async -> consumers (count 64)
#define MB_EMPTY(s)  (SM_MBAR + 32 + (s) * 8)    // consumers -> producer (count 8)

// ---------------------------------------------------------------------------
__device__ __forceinline__ uint32_t smem_u32(const void* p) {
    uint32_t a;
    asm("{ .reg .u64 t; cvta.to.shared.u64 t, %1; cvt.u32.u64 %0, t; }" : "=r"(a) : "l"(p));
    return a;
}
__device__ __forceinline__ float tanh_fast(float x) {
    float y;
    asm("tanh.approx.f32 %0, %1;" : "=f"(y) : "f"(x));
    return y;
}
#define LDSM4(r0, r1, r2, r3, addr) \
    asm volatile("ldmatrix.sync.aligned.m8n8.x4.shared.b16 {%0,%1,%2,%3}, [%4];" \
                 : "=r"(r0), "=r"(r1), "=r"(r2), "=r"(r3) : "r"(addr))
#define MMA16816(c0, c1, c2, c3, a0, a1, a2, a3, b0, b1) \
    asm volatile("mma.sync.aligned.m16n8k16.row.col.f32.bf16.bf16.f32 " \
                 "{%0,%1,%2,%3}, {%4,%5,%6,%7}, {%8,%9}, {%0,%1,%2,%3};" \
                 : "+f"(c0), "+f"(c1), "+f"(c2), "+f"(c3) \
                 : "r"(a0), "r"(a1), "r"(a2), "r"(a3), "r"(b0), "r"(b1))
#define MBAR_INIT(a, n) \
    asm volatile("mbarrier.init.shared.b64 [%0], %1;" :: "r"(a), "r"((uint32_t)(n)) : "memory")
#define MBAR_ARRIVE(a) \
    asm volatile("mbarrier.arrive.shared.b64 _, [%0];" :: "r"(a) : "memory")
#define MBAR_WAIT(a, p) do {                                                   \
    uint32_t _d;                                                               \
    asm volatile("{.reg .pred P;\n"                                            \
        "mbarrier.try_wait.parity.acquire.cta.shared::cta.b64 P, [%1], %2;\n"  \
        "selp.b32 %0, 1, 0, P;}" : "=r"(_d) : "r"((uint32_t)(a)), "r"((uint32_t)(p)) : "memory"); \
    while (!_d) {                                                              \
        asm volatile("{.reg .pred P;\n"                                        \
            "mbarrier.try_wait.parity.acquire.cta.shared::cta.b64 P, [%1], %2, 0x989680;\n" \
            "selp.b32 %0, 1, 0, P;}" : "=r"(_d) : "r"((uint32_t)(a)), "r"((uint32_t)(p)) : "memory"); \
    } } while (0)

// ---------------------------------------------------------------------------
// Fused prep: blocks [0,512) qproj, [512,1024) wkconv, [1024,1280) zero out
__global__ void prep_kernel(const float* __restrict__ query,
                            const float* __restrict__ Wq,
                            const float* __restrict__ bq,
                            const float* __restrict__ bk,
                            const float* __restrict__ Wk,
                            float* __restrict__ out) {
    int bid = blockIdx.x;
    int tid = threadIdx.x;
    if (bid < 512) {
        int b = bid >> 3, oct = bid & 7;
        int lane = tid & 31, w = tid >> 5;
        __shared__ float qs[KD_];
        for (int i = tid; i < KD_; i += 256) qs[i] = query[b * KD_ + i];
        __syncthreads();
        for (int it = 0; it < 16; ++it) {
            int u = oct * 128 + it * 8 + w;
            const float* wr = Wq + (size_t)u * KD_;
            float p = 0.f;
            #pragma unroll 4
            for (int k = lane; k < KD_; k += 32) p += qs[k] * wr[k];
            p += __shfl_xor_sync(~0u, p, 16);
            p += __shfl_xor_sync(~0u, p, 8);
            p += __shfl_xor_sync(~0u, p, 4);
            p += __shfl_xor_sync(~0u, p, 2);
            p += __shfl_xor_sync(~0u, p, 1);
            if (lane == 0) g_qb[b * U_ + u] = p + bq[u] + bk[u];
        }
    } else if (bid < 1024) {
        int i4 = (bid - 512) * 256 + tid;       // 131072 float4 groups
        float4 f = ((const float4*)Wk)[i4];
        __nv_bfloat162 p0 = __floats2bfloat162_rn(f.x, f.y);
        __nv_bfloat162 p1 = __floats2bfloat162_rn(f.z, f.w);
        uint2 val = make_uint2(*(uint32_t*)&p0, *(uint32_t*)&p1);
        *(uint2*)(g_wkb + (size_t)i4 * 4) = val;
    } else {
        int i4 = (bid - 1024) * 256 + tid;      // 65536 float4 = 262144 floats
        ((float4*)out)[i4] = make_float4(0.f, 0.f, 0.f, 0.f);
    }
}

// ---------------------------------------------------------------------------
__global__ void __launch_bounds__(NT_MAIN, 1)
main_kernel(const float* __restrict__ key,
            const float* __restrict__ v,
            float* __restrict__ out) {
    extern __shared__ char smem[];
    const uint32_t smb = smem_u32(smem);
    __nv_bfloat16* keys = (__nv_bfloat16*)(smem + SM_KEYS);
    float* qb_s  = (float*)(smem + SM_QB);
    float* nv_s  = (float*)(smem + SM_NV);
    float* add_s = (float*)(smem + SM_ADD);
    float* tmp_s = (float*)(smem + SM_TMP);

    int bid = blockIdx.x;
    int b = bid >> 4, tt = bid & 15;
    int tid = threadIdx.x, lane = tid & 31, w = tid >> 5;   // 10 warps

    const float* keyg = key + ((size_t)(b * TK_ + tt * TT_)) * KD_;

    // ---- init phase (all 320 threads) ----
    {   // key tile fp32 -> bf16 smem (pitch KPAD_)
        const float4* kg4 = (const float4*)keyg;
        for (int i = tid; i < TT_ * KD_ / 4; i += NT_MAIN) {
            int row = i >> 7, c4 = i & 127;
            float4 f = kg4[row * 128 + c4];
            __nv_bfloat162* dst = (__nv_bfloat162*)(keys + row * KPAD_ + c4 * 4);
            dst[0] = __floats2bfloat162_rn(f.x, f.y);
            dst[1] = __floats2bfloat162_rn(f.z, f.w);
        }
    }
    for (int i = tid; i < U_; i += NT_MAIN) qb_s[i] = g_qb[b * U_ + i];
    for (int i = tid; i < H_ * TT_; i += NT_MAIN) add_s[i] = 0.f;
    if (w == 0) {
        float p = 0.f;
        #pragma unroll
        for (int j = 0; j < 4; ++j) { float x = v[lane + 32 * j]; p += x * x; }
        p += __shfl_xor_sync(~0u, p, 16);
        p += __shfl_xor_sync(~0u, p, 8);
        p += __shfl_xor_sync(~0u, p, 4);
        p += __shfl_xor_sync(~0u, p, 2);
        p += __shfl_xor_sync(~0u, p, 1);
        if (lane == 0) tmp_s[0] = rsqrtf(p) * 0.08838834764831845f;  // 1/sqrt(128)
    }
    if (tid == 0) {
        #pragma unroll
        for (int s = 0; s < 4; ++s) {
            MBAR_INIT(smb + MB_FULL(s), 64);   // 64 producer threads, noinc cp.async arrive
            MBAR_INIT(smb + MB_EMPTY(s), 8);   // 8 consumer warps lane-0 arrive
        }
    }
    __syncthreads();
    if (tid < D_) nv_s[tid] = v[tid] * tmp_s[0];
    __syncthreads();

    if (w >= 8) {
        // ===================== producer warps (64 threads) =====================
        int ptid = tid - 256;   // 0..63
        for (int c = 0; c < 64; ++c) {
            int s = c & 3, r = c >> 2, h = c >> 3, kc = c & 7;
            MBAR_WAIT(smb + MB_EMPTY(s), (r & 1) ^ 1);   // fresh barrier passes (parity 1)
            const __nv_bfloat16* src = g_wkb + (size_t)h * D_ * KD_ + kc * 64;
            uint32_t dst0 = smb + SM_WK + s * WKSTG_;
            #pragma unroll
            for (int j = 0; j < 16; ++j) {
                int i = ptid + j * 64;
                int rr = i >> 3, g = i & 7;
                const void* gp = src + (size_t)rr * KD_ + g * 8;
                asm volatile("cp.async.cg.shared.global [%0], [%1], 16;"
                             :: "r"(dst0 + rr * (WKPAD_ * 2) + g * 16), "l"(gp));
            }
            // noinc: arrival counts against the init count (plain form nets zero!)
            asm volatile("cp.async.mbarrier.arrive.noinc.shared.b64 [%0];"
                         :: "r"(smb + MB_FULL(s)) : "memory");
        }
    } else {
        // ===================== consumer warps 0-7 =====================
        int wm = w & 1, wn = w >> 1;   // 2 warps on M (64 rows), 4 on N (32 cols)

        // ldmatrix base addresses
        uint32_t a_base = smb + SM_KEYS
                        + (uint32_t)(wm * 64 + (lane & 15)) * (KPAD_ * 2)
                        + (uint32_t)(lane >> 4) * 16;
        uint32_t b_base = smb + SM_WK
                        + (uint32_t)(wn * 32 + (lane & 7) + ((lane >> 4) & 1) * 8) * (WKPAD_ * 2)
                        + (uint32_t)((lane >> 3) & 1) * 16;

        // hoisted nv fragment values (head-invariant)
        float nvr0[4], nvr1[4];
        int ubase = wn * 32 + (lane & 3) * 2;
        #pragma unroll
        for (int nt = 0; nt < 4; ++nt) {
            nvr0[nt] = nv_s[ubase + nt * 8];
            nvr1[nt] = nv_s[ubase + nt * 8 + 1];
        }

        float c_[4][4][4];      // [mt][nt][e]
        #pragma unroll
        for (int mt = 0; mt < 4; ++mt)
            #pragma unroll
            for (int nt = 0; nt < 4; ++nt)
                #pragma unroll
                for (int e = 0; e < 4; ++e) c_[mt][nt][e] = 0.f;

        uint32_t af[2][4][4];   // [buf][mt][frag]
        uint32_t bf[2][2][4];   // [buf][p][frag]

        for (int c = 0; c < 64; ++c) {
            int s = c & 3, r = c >> 2;
            MBAR_WAIT(smb + MB_FULL(s), r & 1);

            uint32_t bst = b_base + (uint32_t)s * WKSTG_;
            uint32_t ast = a_base + (uint32_t)((c & 7) * 64) * 2;

            // load k-step 0 fragments into buf 0
            #pragma unroll
            for (int mt = 0; mt < 4; ++mt)
                LDSM4(af[0][mt][0], af[0][mt][1], af[0][mt][2], af[0][mt][3],
                      ast + (uint32_t)(mt * 16) * (KPAD_ * 2));
            #pragma unroll
            for (int p = 0; p < 2; ++p)
                LDSM4(bf[0][p][0], bf[0][p][1], bf[0][p][2], bf[0][p][3],
                      bst + (uint32_t)(p * 16) * (WKPAD_ * 2));

            #pragma unroll
            for (int ks = 0; ks < 4; ++ks) {
                int cur = ks & 1, nxt = cur ^ 1;
                if (ks < 3) {   // prefetch next k-step fragments
                    uint32_t ao = ast + (uint32_t)((ks + 1) * 16) * 2;
                    #pragma unroll
                    for (int mt = 0; mt < 4; ++mt)
                        LDSM4(af[nxt][mt][0], af[nxt][mt][1], af[nxt][mt][2], af[nxt][mt][3],
                              ao + (uint32_t)(mt * 16) * (KPAD_ * 2));
                    uint32_t bo = bst + (uint32_t)((ks + 1) * 16) * 2;
                    #pragma unroll
                    for (int p = 0; p < 2; ++p)
                        LDSM4(bf[nxt][p][0], bf[nxt][p][1], bf[nxt][p][2], bf[nxt][p][3],
                              bo + (uint32_t)(p * 16) * (WKPAD_ * 2));
                }
                #pragma unroll
                for (int mt = 0; mt < 4; ++mt)
                    #pragma unroll
                    for (int nt = 0; nt < 4; ++nt) {
                        uint32_t b0 = (nt & 1) ? bf[cur][nt >> 1][2] : bf[cur][nt >> 1][0];
                        uint32_t b1 = (nt & 1) ? bf[cur][nt >> 1][3] : bf[cur][nt >> 1][1];
                        MMA16816(c_[mt][nt][0], c_[mt][nt][1], c_[mt][nt][2], c_[mt][nt][3],
                                 af[cur][mt][0], af[cur][mt][1], af[cur][mt][2], af[cur][mt][3],
                                 b0, b1);
                    }
            }
            // all LDSM outputs consumed by MMAs -> stage-s smem reads complete
            if (lane == 0) MBAR_ARRIVE(smb + MB_EMPTY(s));

            if ((c & 7) == 7) {
                // epilogue: add_s[h][t] += sum_u nv[u] * tanh(kp + q)
                int h = c >> 3;
                const float* qh = qb_s + h * D_;
                #pragma unroll
                for (int mt = 0; mt < 4; ++mt) {
                    float slo = 0.f, shi = 0.f;
                    #pragma unroll
                    for (int nt = 0; nt < 4; ++nt) {
                        int u0 = ubase + nt * 8;
                        float q0 = qh[u0], q1 = qh[u0 + 1];
                        slo += nvr0[nt] * tanh_fast(c_[mt][nt][0] + q0)
                             + nvr1[nt] * tanh_fast(c_[mt][nt][1] + q1);
                        shi += nvr0[nt] * tanh_fast(c_[mt][nt][2] + q0)
                             + nvr1[nt] * tanh_fast(c_[mt][nt][3] + q1);
                        c_[mt][nt][0] = 0.f; c_[mt][nt][1] = 0.f;
                        c_[mt][nt][2] = 0.f; c_[mt][nt][3] = 0.f;
                    }
                    slo += __shfl_xor_sync(~0u, slo, 1);
                    slo += __shfl_xor_sync(~0u, slo, 2);
                    shi += __shfl_xor_sync(~0u, shi, 1);
                    shi += __shfl_xor_sync(~0u, shi, 2);
                    if ((lane & 3) == 0) {
                        int rrow = wm * 64 + mt * 16 + (lane >> 2);
                        atomicAdd(&add_s[h * TT_ + rrow], slo);
                        atomicAdd(&add_s[h * TT_ + rrow + 8], shi);
                    }
                }
            }
        }
    }
    __syncthreads();

    // ---- softmax over heads (legacy dim=1) ----
    if (tid < TT_) {
        float av[H_];
        float m = -1e30f;
        #pragma unroll
        for (int h = 0; h < H_; ++h) { av[h] = add_s[h * TT_ + tid]; m = fmaxf(m, av[h]); }
        float s = 0.f;
        #pragma unroll
        for (int h = 0; h < H_; ++h) { av[h] = __expf(av[h] - m); s += av[h]; }
        float inv = __fdividef(1.0f, s);
        #pragma unroll
        for (int h = 0; h < H_; ++h) add_s[h * TT_ + tid] = av[h] * inv;
    }
    __syncthreads();

    // ---- context: out[b,h,d] += sum_t w[h,t] * key[t,d] (fp32 key from L2) ----
    if (tid < 256) {
        float acc[H_][2];
        #pragma unroll
        for (int h = 0; h < H_; ++h) { acc[h][0] = 0.f; acc[h][1] = 0.f; }
        const float2* kg2 = (const float2*)keyg;
        for (int t = 0; t < TT_; ++t) {
            float2 kv = kg2[t * (KD_ / 2) + tid];
            #pragma unroll
            for (int h = 0; h < H_; ++h) {
                float wv = add_s[h * TT_ + t];
                acc[h][0] += wv * kv.x;
                acc[h][1] += wv * kv.y;
            }
        }
        float* ob = out + (size_t)b * (H_ * KD_) + tid * 2;
        #pragma unroll
        for (int h = 0; h < H_; ++h) {
            atomicAdd(&ob[h * KD_], acc[h][0]);
            atomicAdd(&ob[h * KD_ + 1], acc[h][1]);
        }
    }
}

// ---------------------------------------------------------------------------
extern "C" void kernel_launch(void* const* d_in, const int* in_sizes, int n_in,
                              void* d_out, int out_size) {
    const float* query = (const float*)d_in[0];
    const float* key   = (const float*)d_in[1];
    const float* Wq    = (const float*)d_in[2];
    const float* bq    = (const float*)d_in[3];
    const float* Wk    = (const float*)d_in[4];
    const float* bk    = (const float*)d_in[5];
    const float* v     = (const float*)d_in[6];
    float* out = (float*)d_out;

    prep_kernel<<<1280, 256>>>(query, Wq, bq, bk, Wk, out);

    cudaFuncSetAttribute(main_kernel,
                         cudaFuncAttributeMaxDynamicSharedMemorySize, SM_TOTAL);
    main_kernel<<<B_ * (TK_ / TT_), NT_MAIN, SM_TOTAL>>>(key, v, out);
}